// round 3
// baseline (speedup 1.0000x reference)
#include <cuda_runtime.h>
#include <cstdint>
#include <cstring>
#include <math.h>

// Problem dims
#define BB 4
#define SS 2048
#define DD 768
#define HH 12
#define DKK 64

typedef unsigned long long ull;

static const long long OUT_ELEMS  = (long long)BB * SS * DD;          // 6291456
static const long long ATTN_ELEMS = (long long)BB * HH * SS * SS;     // 201326592

// Scratch (device globals: allowed; no runtime allocation)
__device__ float g_q[BB * HH * SS * DKK];
__device__ float g_k[BB * HH * SS * DKK];
__device__ float g_v[BB * HH * SS * DKK];
__device__ float g_ctx[BB * SS * DD];
__device__ float g_pre[BB * SS * DD];
__device__ float g_attn_fb[(long long)BB * HH * SS * SS]; // fallback if attn not in d_out

// Packed fp32x2 FMA (Blackwell FFMA2; only reachable via PTX)
#define FFMA2(acc, a, b) \
    asm("fma.rn.f32x2 %0, %1, %2, %3;" : "=l"(acc) : "l"(a), "l"(b), "l"(acc))

__device__ __forceinline__ float2 unpack2(ull u) { float2 f; memcpy(&f, &u, 8); return f; }

// ---------------------------------------------------------------------------
// Projection / output GEMM:  Y = X[8192,768] @ W[768,768] + bias (+resid)
// MODE 0/1/2: write q/k/v in [B,H,S,DK] layout. MODE 3: X=g_ctx, +resid -> g_pre
// BM=128, BN=64, BK=16, 256 threads, 8x4 per thread, FFMA2 inner loop.
// A stored DUPLICATED in smem so packed pairs load directly.
// ---------------------------------------------------------------------------
template <int MODE>
__global__ void __launch_bounds__(256) gemm768_kernel(
    const float* __restrict__ Xext, const float* __restrict__ W,
    const float* __restrict__ bias, const float* __restrict__ resid)
{
    const float* X = (MODE == 3) ? g_ctx : Xext;
    float* Y = (MODE == 0) ? g_q : (MODE == 1) ? g_k : (MODE == 2) ? g_v : g_pre;

    __shared__ float As2[16][260];  // [k][2*m (+dup)], stride even for 8B loads
    __shared__ float Bs[16][64];

    const int tid  = threadIdx.x;
    const int m0   = blockIdx.y * 128;
    const int n0   = blockIdx.x * 64;
    const int trow = (tid / 16) * 8;
    const int tcol = (tid % 16) * 4;

    ull acc2[8][2];
    #pragma unroll
    for (int i = 0; i < 8; i++) { acc2[i][0] = 0ull; acc2[i][1] = 0ull; }

    for (int k0 = 0; k0 < DD; k0 += 16) {
        // A tile 128x16 -> transposed + duplicated store
        #pragma unroll
        for (int t = 0; t < 2; t++) {
            int e = (tid + t * 256) * 4;
            int r = e / 16, c = e % 16;
            float4 v = *reinterpret_cast<const float4*>(X + (size_t)(m0 + r) * DD + k0 + c);
            As2[c + 0][2*r] = v.x; As2[c + 0][2*r + 1] = v.x;
            As2[c + 1][2*r] = v.y; As2[c + 1][2*r + 1] = v.y;
            As2[c + 2][2*r] = v.z; As2[c + 2][2*r + 1] = v.z;
            As2[c + 3][2*r] = v.w; As2[c + 3][2*r + 1] = v.w;
        }
        // B tile 16x64
        {
            int e = tid * 4;
            int r = e / 64, c = e % 64;
            *reinterpret_cast<float4*>(&Bs[r][c]) =
                *reinterpret_cast<const float4*>(W + (size_t)(k0 + r) * DD + n0 + c);
        }
        __syncthreads();
        #pragma unroll
        for (int kk = 0; kk < 16; kk++) {
            ull a2[8], b2[2];
            const ull* ap = reinterpret_cast<const ull*>(&As2[kk][2 * trow]);
            #pragma unroll
            for (int i = 0; i < 8; i++) a2[i] = ap[i];
            const ull* bp = reinterpret_cast<const ull*>(&Bs[kk][tcol]);
            b2[0] = bp[0]; b2[1] = bp[1];
            #pragma unroll
            for (int i = 0; i < 8; i++) {
                FFMA2(acc2[i][0], a2[i], b2[0]);
                FFMA2(acc2[i][1], a2[i], b2[1]);
            }
        }
        __syncthreads();
    }

    #pragma unroll
    for (int i = 0; i < 8; i++) {
        int r = m0 + trow + i;
        float accr[4];
        { float2 f0 = unpack2(acc2[i][0]), f1 = unpack2(acc2[i][1]);
          accr[0] = f0.x; accr[1] = f0.y; accr[2] = f1.x; accr[3] = f1.y; }
        #pragma unroll
        for (int j = 0; j < 4; j++) {
            int c = n0 + tcol + j;
            float v = accr[j] + bias[c];
            if (MODE <= 2) {
                int b_ = r / SS, s = r % SS;
                int h = c / DKK, d = c % DKK;
                Y[(((size_t)b_ * HH + h) * SS + s) * DKK + d] = v;
            } else {
                v += resid[(size_t)r * DD + c];
                Y[(size_t)r * DD + c] = v;
            }
        }
    }
}

// ---------------------------------------------------------------------------
// Scores: per (b,h): S[q,k] = (q . k) / 8, masked (int32 mask). 128x128 tile.
// Q side duplicated in smem for FFMA2.
// ---------------------------------------------------------------------------
__global__ void __launch_bounds__(256) scores_kernel(
    const int* __restrict__ pad, float* __restrict__ attn_ext)
{
    float* attn = attn_ext ? attn_ext : g_attn_fb;
    extern __shared__ float smem[];
    float (*Qs2)[258] = reinterpret_cast<float(*)[258]>(smem);              // [64][2*128+pad]
    float (*Ks)[130]  = reinterpret_cast<float(*)[130]>(smem + 64 * 258);   // [64][128+pad]

    const int bh = blockIdx.z;
    const int b_ = bh / HH;
    const int q0 = blockIdx.y * 128;
    const int k0 = blockIdx.x * 128;
    const int tid = threadIdx.x;

    const float* qp = g_q + ((size_t)bh * SS + q0) * DKK;
    const float* kp = g_k + ((size_t)bh * SS + k0) * DKK;

    // load 128x64 q/k tiles, transposed ([d][row]); Q duplicated
    #pragma unroll
    for (int t = 0; t < 8; t++) {
        int e = (tid + t * 256) * 4;
        int r = e / 64, c = e % 64;
        float4 v = *reinterpret_cast<const float4*>(qp + (size_t)r * DKK + c);
        Qs2[c + 0][2*r] = v.x; Qs2[c + 0][2*r + 1] = v.x;
        Qs2[c + 1][2*r] = v.y; Qs2[c + 1][2*r + 1] = v.y;
        Qs2[c + 2][2*r] = v.z; Qs2[c + 2][2*r + 1] = v.z;
        Qs2[c + 3][2*r] = v.w; Qs2[c + 3][2*r + 1] = v.w;
        float4 w = *reinterpret_cast<const float4*>(kp + (size_t)r * DKK + c);
        Ks[c + 0][r] = w.x; Ks[c + 1][r] = w.y; Ks[c + 2][r] = w.z; Ks[c + 3][r] = w.w;
    }
    __syncthreads();

    const int trow = (tid / 16) * 8;
    const int tcol = (tid % 16) * 8;
    ull acc2[8][4];
    #pragma unroll
    for (int i = 0; i < 8; i++)
        #pragma unroll
        for (int j = 0; j < 4; j++) acc2[i][j] = 0ull;

    #pragma unroll
    for (int kk = 0; kk < 64; kk++) {
        ull a2[8], b2[4];
        const ull* ap = reinterpret_cast<const ull*>(&Qs2[kk][2 * trow]);
        #pragma unroll
        for (int i = 0; i < 8; i++) a2[i] = ap[i];
        const ull* bp = reinterpret_cast<const ull*>(&Ks[kk][tcol]);
        #pragma unroll
        for (int j = 0; j < 4; j++) b2[j] = bp[j];
        #pragma unroll
        for (int i = 0; i < 8; i++)
            #pragma unroll
            for (int j = 0; j < 4; j++) FFMA2(acc2[i][j], a2[i], b2[j]);
    }

    const size_t base = (size_t)bh * SS * SS;
    #pragma unroll
    for (int i = 0; i < 8; i++) {
        int qr = q0 + trow + i;
        const size_t midx = ((size_t)b_ * SS + qr) * SS + k0 + tcol;
        const int4* pi = reinterpret_cast<const int4*>(pad + midx);
        int4 a4 = pi[0], b4 = pi[1];
        int m[8] = {a4.x, a4.y, a4.z, a4.w, b4.x, b4.y, b4.z, b4.w};
        float acc[8];
        #pragma unroll
        for (int j = 0; j < 4; j++) {
            float2 f = unpack2(acc2[i][j]);
            acc[2*j] = f.x; acc[2*j + 1] = f.y;
        }
        float* orow = attn + base + (size_t)qr * SS + k0 + tcol;
        #pragma unroll
        for (int j = 0; j < 8; j++) {
            float v = acc[j] * 0.125f;
            if (m[j]) v = -1e9f;
            orow[j] = v;
        }
    }
}

// ---------------------------------------------------------------------------
// Row softmax over 2048, one block per row, in-place.
// ---------------------------------------------------------------------------
__global__ void __launch_bounds__(256) softmax_kernel(float* __restrict__ attn_ext)
{
    float* attn = attn_ext ? attn_ext : g_attn_fb;
    const size_t row = blockIdx.x;
    float* p = attn + row * SS;
    const int tid = threadIdx.x;

    __shared__ float red[8];
    float vals[8];
    float mx = -INFINITY;
    #pragma unroll
    for (int t = 0; t < 8; t++) { vals[t] = p[tid + t * 256]; mx = fmaxf(mx, vals[t]); }
    #pragma unroll
    for (int o = 16; o; o >>= 1) mx = fmaxf(mx, __shfl_xor_sync(~0u, mx, o));
    if ((tid & 31) == 0) red[tid >> 5] = mx;
    __syncthreads();
    mx = red[0];
    #pragma unroll
    for (int w = 1; w < 8; w++) mx = fmaxf(mx, red[w]);
    __syncthreads();

    float sum = 0.f;
    #pragma unroll
    for (int t = 0; t < 8; t++) { vals[t] = __expf(vals[t] - mx); sum += vals[t]; }
    #pragma unroll
    for (int o = 16; o; o >>= 1) sum += __shfl_xor_sync(~0u, sum, o);
    if ((tid & 31) == 0) red[tid >> 5] = sum;
    __syncthreads();
    sum = 0.f;
    #pragma unroll
    for (int w = 0; w < 8; w++) sum += red[w];
    const float inv = 1.0f / sum;
    #pragma unroll
    for (int t = 0; t < 8; t++) p[tid + t * 256] = vals[t] * inv;
}

// ---------------------------------------------------------------------------
// Context: per (b,h): ctx[q,d] = attn[q,:] @ v[:,d]. BM=128, BN=64, BK=64.
// Attn side duplicated in smem for FFMA2. Writes into [B,S,H*DV] layout.
// ---------------------------------------------------------------------------
__global__ void __launch_bounds__(256) context_kernel(const float* __restrict__ attn_ext)
{
    const float* attn = attn_ext ? attn_ext : g_attn_fb;
    extern __shared__ float smem[];
    float (*Ast2)[258] = reinterpret_cast<float(*)[258]>(smem);           // [64][2*128+pad]
    float (*Vs)[64]    = reinterpret_cast<float(*)[64]>(smem + 64 * 258); // [64][64]

    const int bh = blockIdx.y;
    const int q0 = blockIdx.x * 128;
    const int tid = threadIdx.x;
    const int trow = (tid / 16) * 8;
    const int tcol = (tid % 16) * 4;

    const float* ap_g = attn + ((size_t)bh * SS + q0) * SS;
    const float* vp = g_v + (size_t)bh * SS * DKK;

    ull acc2[8][2];
    #pragma unroll
    for (int i = 0; i < 8; i++) { acc2[i][0] = 0ull; acc2[i][1] = 0ull; }

    for (int k0 = 0; k0 < SS; k0 += 64) {
        #pragma unroll
        for (int t = 0; t < 8; t++) {
            int e = (tid + t * 256) * 4;
            int r = e / 64, c = e % 64;
            float4 v = *reinterpret_cast<const float4*>(ap_g + (size_t)r * SS + k0 + c);
            Ast2[c + 0][2*r] = v.x; Ast2[c + 0][2*r + 1] = v.x;
            Ast2[c + 1][2*r] = v.y; Ast2[c + 1][2*r + 1] = v.y;
            Ast2[c + 2][2*r] = v.z; Ast2[c + 2][2*r + 1] = v.z;
            Ast2[c + 3][2*r] = v.w; Ast2[c + 3][2*r + 1] = v.w;
        }
        #pragma unroll
        for (int t = 0; t < 4; t++) {
            int e = (tid + t * 256) * 4;
            int r = e / 64, c = e % 64;
            *reinterpret_cast<float4*>(&Vs[r][c]) =
                *reinterpret_cast<const float4*>(vp + (size_t)(k0 + r) * DKK + c);
        }
        __syncthreads();
        #pragma unroll
        for (int kk = 0; kk < 64; kk++) {
            ull a2[8], b2[2];
            const ull* ap = reinterpret_cast<const ull*>(&Ast2[kk][2 * trow]);
            #pragma unroll
            for (int i = 0; i < 8; i++) a2[i] = ap[i];
            const ull* bp = reinterpret_cast<const ull*>(&Vs[kk][tcol]);
            b2[0] = bp[0]; b2[1] = bp[1];
            #pragma unroll
            for (int i = 0; i < 8; i++) {
                FFMA2(acc2[i][0], a2[i], b2[0]);
                FFMA2(acc2[i][1], a2[i], b2[1]);
            }
        }
        __syncthreads();
    }

    const int b_ = bh / HH, h = bh % HH;
    #pragma unroll
    for (int i = 0; i < 8; i++) {
        int s = q0 + trow + i;
        float2 f0 = unpack2(acc2[i][0]), f1 = unpack2(acc2[i][1]);
        float* orow = &g_ctx[((size_t)b_ * SS + s) * DD + h * DKK + tcol];
        orow[0] = f0.x; orow[1] = f0.y; orow[2] = f1.x; orow[3] = f1.y;
    }
}

// ---------------------------------------------------------------------------
// LayerNorm over D=768, one block per row.
// ---------------------------------------------------------------------------
__global__ void __launch_bounds__(256) ln_kernel(
    const float* __restrict__ lg, const float* __restrict__ lb, float* __restrict__ out)
{
    const size_t row = blockIdx.x;
    const float* x = g_pre + row * DD;
    const int tid = threadIdx.x;
    __shared__ float red[8];

    float v[3];
    float s = 0.f;
    #pragma unroll
    for (int t = 0; t < 3; t++) { v[t] = x[tid + t * 256]; s += v[t]; }
    #pragma unroll
    for (int o = 16; o; o >>= 1) s += __shfl_xor_sync(~0u, s, o);
    if ((tid & 31) == 0) red[tid >> 5] = s;
    __syncthreads();
    s = 0.f;
    #pragma unroll
    for (int w = 0; w < 8; w++) s += red[w];
    const float mu = s * (1.0f / DD);
    __syncthreads();

    float var = 0.f;
    #pragma unroll
    for (int t = 0; t < 3; t++) { float d = v[t] - mu; var += d * d; }
    #pragma unroll
    for (int o = 16; o; o >>= 1) var += __shfl_xor_sync(~0u, var, o);
    if ((tid & 31) == 0) red[tid >> 5] = var;
    __syncthreads();
    var = 0.f;
    #pragma unroll
    for (int w = 0; w < 8; w++) var += red[w];
    const float inv = rsqrtf(var * (1.0f / DD) + 1e-5f);

    #pragma unroll
    for (int t = 0; t < 3; t++) {
        int c = tid + t * 256;
        out[row * DD + c] = (v[t] - mu) * inv * lg[c] + lb[c];
    }
}

// ---------------------------------------------------------------------------
extern "C" void kernel_launch(void* const* d_in, const int* in_sizes, int n_in,
                              void* d_out, int out_size)
{
    const float* Q  = (const float*)d_in[0];
    const float* K  = (const float*)d_in[1];
    const float* V  = (const float*)d_in[2];
    const int*   pad = (const int*)d_in[3];
    const float* Wq = (const float*)d_in[4];
    const float* bq = (const float*)d_in[5];
    const float* Wk = (const float*)d_in[6];
    const float* bk = (const float*)d_in[7];
    const float* Wv = (const float*)d_in[8];
    const float* bv = (const float*)d_in[9];
    const float* Wo = (const float*)d_in[10];
    const float* bo = (const float*)d_in[11];
    const float* lg = (const float*)d_in[12];
    const float* lb = (const float*)d_in[13];
    float* out = (float*)d_out;

    // If d_out holds (out, attn) concatenated, write attn straight into it.
    float* attn = ((long long)out_size >= OUT_ELEMS + ATTN_ELEMS) ? (out + OUT_ELEMS)
                                                                  : nullptr; // use g_attn_fb

    const int SCORES_SMEM = (64 * 258 + 64 * 130) * 4;      // 99328
    const int CTX_SMEM    = (64 * 258 + 64 * 64) * 4;       // 82432
    cudaFuncSetAttribute(scores_kernel, cudaFuncAttributeMaxDynamicSharedMemorySize, SCORES_SMEM);
    cudaFuncSetAttribute(context_kernel, cudaFuncAttributeMaxDynamicSharedMemorySize, CTX_SMEM);

    dim3 gp(DD / 64, (BB * SS) / 128);          // (12, 64)
    gemm768_kernel<0><<<gp, 256>>>(Q, Wq, bq, nullptr);
    gemm768_kernel<1><<<gp, 256>>>(K, Wk, bk, nullptr);
    gemm768_kernel<2><<<gp, 256>>>(V, Wv, bv, nullptr);

    dim3 gs(SS / 128, SS / 128, BB * HH);       // (16, 16, 48)
    scores_kernel<<<gs, 256, SCORES_SMEM>>>(pad, attn);

    softmax_kernel<<<BB * HH * SS, 256>>>(attn);

    dim3 gc(SS / 128, BB * HH);                 // (16, 48)
    context_kernel<<<gc, 256, CTX_SMEM>>>(attn);

    gemm768_kernel<3><<<gp, 256>>>(nullptr, Wo, bo, Q);

    ln_kernel<<<BB * SS, 256>>>(lg, lb, out);
}

// round 4
// speedup vs baseline: 2.1798x; 2.1798x over previous
#include <cuda_runtime.h>
#include <cstdint>
#include <math.h>

#define BB 4
#define SS 2048
#define DD 768
#define HH 12
#define DKK 64

static const long long OUT_ELEMS  = (long long)BB * SS * DD;
static const long long ATTN_ELEMS = (long long)BB * HH * SS * SS;

// Scratch
__device__ float g_q[BB * HH * SS * DKK];
__device__ float g_k[BB * HH * SS * DKK];
__device__ float g_v[BB * HH * SS * DKK];
__device__ float g_ctx[BB * SS * DD];
__device__ float g_pre[BB * SS * DD];
__device__ float g_psum[(size_t)BB * HH * SS * 32];
__device__ float g_rowinv[(size_t)BB * HH * SS];
__device__ float g_attn_fb[(long long)BB * HH * SS * SS];

__device__ __forceinline__ uint32_t cvt_tf32(float x) {
    uint32_t u; asm("cvt.rna.tf32.f32 %0, %1;" : "=r"(u) : "f"(x)); return u;
}

// D = A(16x8,row) * B(8x8,col) + D, tf32 in, fp32 accum
__device__ __forceinline__ void mma8(float* c, const uint32_t* a, const uint32_t* b) {
    asm("mma.sync.aligned.m16n8k8.row.col.f32.tf32.tf32.f32 "
        "{%0,%1,%2,%3},{%4,%5,%6,%7},{%8,%9},{%0,%1,%2,%3};"
        : "+f"(c[0]), "+f"(c[1]), "+f"(c[2]), "+f"(c[3])
        : "r"(a[0]), "r"(a[1]), "r"(a[2]), "r"(a[3]), "r"(b[0]), "r"(b[1]));
}

// ---------------------------------------------------------------------------
// Projection / output GEMM via tf32 MMA.
// Y[8192,768] = X @ W + bias (+resid). Block tile 128x64, warp 32x32, k-chunk 64.
// MODE 0/1/2 -> q/k/v in [B,H,S,DK]; MODE 3 -> g_pre with residual.
// ---------------------------------------------------------------------------
template <int MODE>
__global__ void __launch_bounds__(256) proj_kernel(
    const float* __restrict__ Xext, const float* __restrict__ W,
    const float* __restrict__ bias, const float* __restrict__ resid)
{
    const float* X = (MODE == 3) ? g_ctx : Xext;
    float* Y = (MODE == 0) ? g_q : (MODE == 1) ? g_k : (MODE == 2) ? g_v : g_pre;

    extern __shared__ uint32_t sm[];
    uint32_t (*Xs)[68] = reinterpret_cast<uint32_t(*)[68]>(sm);            // [128][68]
    uint32_t (*Ws)[68] = reinterpret_cast<uint32_t(*)[68]>(sm + 128 * 68); // [64][68]

    const int tid = threadIdx.x, wid = tid >> 5, lane = tid & 31;
    const int gid = lane >> 2, tig = lane & 3;
    const int m0 = blockIdx.y * 128, n0 = blockIdx.x * 64;
    const int wm = (wid >> 1) * 32, wn = (wid & 1) * 32;

    float acc[2][4][4] = {};

    for (int k0 = 0; k0 < DD; k0 += 64) {
        #pragma unroll
        for (int t = 0; t < 8; t++) {
            int e = (tid + t * 256) * 4, r = e >> 6, c = e & 63;
            float4 v = *reinterpret_cast<const float4*>(X + (size_t)(m0 + r) * DD + k0 + c);
            Xs[r][c] = cvt_tf32(v.x); Xs[r][c+1] = cvt_tf32(v.y);
            Xs[r][c+2] = cvt_tf32(v.z); Xs[r][c+3] = cvt_tf32(v.w);
        }
        #pragma unroll
        for (int t = 0; t < 4; t++) {
            int e = (tid + t * 256) * 4, r = e >> 6, c = e & 63;
            float4 v = *reinterpret_cast<const float4*>(W + (size_t)(k0 + r) * DD + n0 + c);
            Ws[r][c] = cvt_tf32(v.x); Ws[r][c+1] = cvt_tf32(v.y);
            Ws[r][c+2] = cvt_tf32(v.z); Ws[r][c+3] = cvt_tf32(v.w);
        }
        __syncthreads();
        #pragma unroll
        for (int kk = 0; kk < 64; kk += 8) {
            uint32_t a[2][4], b[4][2];
            #pragma unroll
            for (int mi = 0; mi < 2; mi++) {
                int r = wm + mi * 16 + gid;
                a[mi][0] = Xs[r][kk + tig];     a[mi][1] = Xs[r + 8][kk + tig];
                a[mi][2] = Xs[r][kk + tig + 4]; a[mi][3] = Xs[r + 8][kk + tig + 4];
            }
            #pragma unroll
            for (int nj = 0; nj < 4; nj++) {
                int n = wn + nj * 8 + gid;
                b[nj][0] = Ws[kk + tig][n]; b[nj][1] = Ws[kk + tig + 4][n];
            }
            #pragma unroll
            for (int mi = 0; mi < 2; mi++)
                #pragma unroll
                for (int nj = 0; nj < 4; nj++) mma8(acc[mi][nj], a[mi], b[nj]);
        }
        __syncthreads();
    }

    #pragma unroll
    for (int mi = 0; mi < 2; mi++)
        #pragma unroll
        for (int rr = 0; rr < 2; rr++) {
            int r = m0 + wm + mi * 16 + gid + rr * 8;
            #pragma unroll
            for (int nj = 0; nj < 4; nj++) {
                int c = n0 + wn + nj * 8 + tig * 2;
                float v0 = acc[mi][nj][rr * 2 + 0] + bias[c];
                float v1 = acc[mi][nj][rr * 2 + 1] + bias[c + 1];
                if (MODE <= 2) {
                    int b_ = r / SS, s = r % SS, h = c / DKK, d = c % DKK;
                    float2* o = reinterpret_cast<float2*>(
                        &Y[(((size_t)b_ * HH + h) * SS + s) * DKK + d]);
                    *o = make_float2(v0, v1);
                } else {
                    const float2 rs = *reinterpret_cast<const float2*>(&resid[(size_t)r * DD + c]);
                    *reinterpret_cast<float2*>(&Y[(size_t)r * DD + c]) =
                        make_float2(v0 + rs.x, v1 + rs.y);
                }
            }
        }
}

// ---------------------------------------------------------------------------
// Scores+exp: per (b,h) 128x128 tile: e = exp((q.k)/8) (0 if masked),
// writes exp to attn buf + per-(row, ktile, warpn) partial sums to g_psum.
// ---------------------------------------------------------------------------
__global__ void __launch_bounds__(256) scores_kernel(
    const int* __restrict__ pad, float* __restrict__ attn_ext)
{
    float* attn = attn_ext ? attn_ext : g_attn_fb;
    extern __shared__ uint32_t sm[];
    uint32_t (*Qs)[68] = reinterpret_cast<uint32_t(*)[68]>(sm);            // [128][68]
    uint32_t (*Ks)[68] = reinterpret_cast<uint32_t(*)[68]>(sm + 128 * 68); // [128][68]

    const int bh = blockIdx.z, b_ = bh / HH;
    const int q0 = blockIdx.y * 128, k0 = blockIdx.x * 128;
    const int tid = threadIdx.x, wid = tid >> 5, lane = tid & 31;
    const int gid = lane >> 2, tig = lane & 3;
    const int wm = (wid >> 1) * 32, wn = (wid & 1) * 64;

    const float* qp = g_q + ((size_t)bh * SS + q0) * DKK;
    const float* kp = g_k + ((size_t)bh * SS + k0) * DKK;

    #pragma unroll
    for (int t = 0; t < 8; t++) {
        int e = (tid + t * 256) * 4, r = e >> 6, c = e & 63;
        float4 v = *reinterpret_cast<const float4*>(qp + (size_t)r * DKK + c);
        Qs[r][c] = cvt_tf32(v.x); Qs[r][c+1] = cvt_tf32(v.y);
        Qs[r][c+2] = cvt_tf32(v.z); Qs[r][c+3] = cvt_tf32(v.w);
        float4 w = *reinterpret_cast<const float4*>(kp + (size_t)r * DKK + c);
        Ks[r][c] = cvt_tf32(w.x); Ks[r][c+1] = cvt_tf32(w.y);
        Ks[r][c+2] = cvt_tf32(w.z); Ks[r][c+3] = cvt_tf32(w.w);
    }
    __syncthreads();

    float acc[2][8][4] = {};
    #pragma unroll
    for (int kk = 0; kk < 64; kk += 8) {
        uint32_t a[2][4], b[8][2];
        #pragma unroll
        for (int mi = 0; mi < 2; mi++) {
            int r = wm + mi * 16 + gid;
            a[mi][0] = Qs[r][kk + tig];     a[mi][1] = Qs[r + 8][kk + tig];
            a[mi][2] = Qs[r][kk + tig + 4]; a[mi][3] = Qs[r + 8][kk + tig + 4];
        }
        #pragma unroll
        for (int nj = 0; nj < 8; nj++) {
            int n = wn + nj * 8 + gid;
            b[nj][0] = Ks[n][kk + tig]; b[nj][1] = Ks[n][kk + tig + 4];
        }
        #pragma unroll
        for (int mi = 0; mi < 2; mi++)
            #pragma unroll
            for (int nj = 0; nj < 8; nj++) mma8(acc[mi][nj], a[mi], b[nj]);
    }

    const size_t base = (size_t)bh * SS * SS;
    #pragma unroll
    for (int mi = 0; mi < 2; mi++)
        #pragma unroll
        for (int rr = 0; rr < 2; rr++) {
            int qr = q0 + wm + mi * 16 + gid + rr * 8;
            float rs = 0.f;
            #pragma unroll
            for (int nj = 0; nj < 8; nj++) {
                int kc = k0 + wn + nj * 8 + tig * 2;
                int2 m2 = *reinterpret_cast<const int2*>(
                    pad + ((size_t)b_ * SS + qr) * SS + kc);
                float v0 = acc[mi][nj][rr * 2 + 0] * 0.125f;
                float v1 = acc[mi][nj][rr * 2 + 1] * 0.125f;
                float p0 = m2.x ? 0.f : __expf(v0);
                float p1 = m2.y ? 0.f : __expf(v1);
                rs += p0 + p1;
                *reinterpret_cast<float2*>(attn + base + (size_t)qr * SS + kc) =
                    make_float2(p0, p1);
            }
            rs += __shfl_xor_sync(~0u, rs, 1);
            rs += __shfl_xor_sync(~0u, rs, 2);
            if (tig == 0)
                g_psum[((size_t)bh * SS + qr) * 32 + blockIdx.x * 2 + (wid & 1)] = rs;
        }
}

// ---------------------------------------------------------------------------
// Row-sum reduce: 1/sum per (bh,row). 98304 rows, 32 partials each.
// ---------------------------------------------------------------------------
__global__ void __launch_bounds__(256) rowinv_kernel()
{
    size_t idx = (size_t)blockIdx.x * 256 + threadIdx.x;
    const float4* p = reinterpret_cast<const float4*>(g_psum + idx * 32);
    float s = 0.f;
    #pragma unroll
    for (int t = 0; t < 8; t++) { float4 v = p[t]; s += v.x + v.y + v.z + v.w; }
    g_rowinv[idx] = 1.0f / s;
}

// ---------------------------------------------------------------------------
// Context: ctx = softmax(attn) @ V. Normalizes exp on load, writes final
// attn back, tf32 MMA accumulate. Block 128(q) x 64(dv), k-chunk 64.
// ---------------------------------------------------------------------------
__global__ void __launch_bounds__(256) context_kernel(float* __restrict__ attn_ext)
{
    float* attn = attn_ext ? attn_ext : g_attn_fb;
    extern __shared__ uint32_t sm[];
    uint32_t (*Ast)[68] = reinterpret_cast<uint32_t(*)[68]>(sm);            // [128][68]
    uint32_t (*Vs)[68]  = reinterpret_cast<uint32_t(*)[68]>(sm + 128 * 68); // [64][68]

    const int bh = blockIdx.y, q0 = blockIdx.x * 128;
    const int tid = threadIdx.x, wid = tid >> 5, lane = tid & 31;
    const int gid = lane >> 2, tig = lane & 3;
    const int wm = (wid >> 1) * 32, wn = (wid & 1) * 32;

    float* ap = attn + ((size_t)bh * SS + q0) * SS;
    const float* vp = g_v + (size_t)bh * SS * DKK;
    const float* invp = g_rowinv + (size_t)bh * SS + q0;

    float acc[2][4][4] = {};

    for (int k0 = 0; k0 < SS; k0 += 64) {
        #pragma unroll
        for (int t = 0; t < 8; t++) {
            int e = (tid + t * 256) * 4, r = e >> 6, c = e & 63;
            float inv = invp[r];
            float* gp = ap + (size_t)r * SS + k0 + c;
            float4 v = *reinterpret_cast<const float4*>(gp);
            v.x *= inv; v.y *= inv; v.z *= inv; v.w *= inv;
            *reinterpret_cast<float4*>(gp) = v;   // final normalized attn
            Ast[r][c] = cvt_tf32(v.x); Ast[r][c+1] = cvt_tf32(v.y);
            Ast[r][c+2] = cvt_tf32(v.z); Ast[r][c+3] = cvt_tf32(v.w);
        }
        #pragma unroll
        for (int t = 0; t < 4; t++) {
            int e = (tid + t * 256) * 4, r = e >> 6, c = e & 63;
            float4 v = *reinterpret_cast<const float4*>(vp + (size_t)(k0 + r) * DKK + c);
            Vs[r][c] = cvt_tf32(v.x); Vs[r][c+1] = cvt_tf32(v.y);
            Vs[r][c+2] = cvt_tf32(v.z); Vs[r][c+3] = cvt_tf32(v.w);
        }
        __syncthreads();
        #pragma unroll
        for (int kk = 0; kk < 64; kk += 8) {
            uint32_t a[2][4], b[4][2];
            #pragma unroll
            for (int mi = 0; mi < 2; mi++) {
                int r = wm + mi * 16 + gid;
                a[mi][0] = Ast[r][kk + tig];     a[mi][1] = Ast[r + 8][kk + tig];
                a[mi][2] = Ast[r][kk + tig + 4]; a[mi][3] = Ast[r + 8][kk + tig + 4];
            }
            #pragma unroll
            for (int nj = 0; nj < 4; nj++) {
                int n = wn + nj * 8 + gid;
                b[nj][0] = Vs[kk + tig][n]; b[nj][1] = Vs[kk + tig + 4][n];
            }
            #pragma unroll
            for (int mi = 0; mi < 2; mi++)
                #pragma unroll
                for (int nj = 0; nj < 4; nj++) mma8(acc[mi][nj], a[mi], b[nj]);
        }
        __syncthreads();
    }

    const int b_ = bh / HH, h = bh % HH;
    #pragma unroll
    for (int mi = 0; mi < 2; mi++)
        #pragma unroll
        for (int rr = 0; rr < 2; rr++) {
            int s = q0 + wm + mi * 16 + gid + rr * 8;
            #pragma unroll
            for (int nj = 0; nj < 4; nj++) {
                int d = wn + nj * 8 + tig * 2;
                *reinterpret_cast<float2*>(&g_ctx[((size_t)b_ * SS + s) * DD + h * DKK + d]) =
                    make_float2(acc[mi][nj][rr * 2], acc[mi][nj][rr * 2 + 1]);
            }
        }
}

// ---------------------------------------------------------------------------
// LayerNorm over D=768.
// ---------------------------------------------------------------------------
__global__ void __launch_bounds__(256) ln_kernel(
    const float* __restrict__ lg, const float* __restrict__ lb, float* __restrict__ out)
{
    const size_t row = blockIdx.x;
    const float* x = g_pre + row * DD;
    const int tid = threadIdx.x;
    __shared__ float red[8];

    float v[3];
    float s = 0.f;
    #pragma unroll
    for (int t = 0; t < 3; t++) { v[t] = x[tid + t * 256]; s += v[t]; }
    #pragma unroll
    for (int o = 16; o; o >>= 1) s += __shfl_xor_sync(~0u, s, o);
    if ((tid & 31) == 0) red[tid >> 5] = s;
    __syncthreads();
    s = 0.f;
    #pragma unroll
    for (int w = 0; w < 8; w++) s += red[w];
    const float mu = s * (1.0f / DD);
    __syncthreads();

    float var = 0.f;
    #pragma unroll
    for (int t = 0; t < 3; t++) { float d = v[t] - mu; var += d * d; }
    #pragma unroll
    for (int o = 16; o; o >>= 1) var += __shfl_xor_sync(~0u, var, o);
    if ((tid & 31) == 0) red[tid >> 5] = var;
    __syncthreads();
    var = 0.f;
    #pragma unroll
    for (int w = 0; w < 8; w++) var += red[w];
    const float inv = rsqrtf(var * (1.0f / DD) + 1e-5f);

    #pragma unroll
    for (int t = 0; t < 3; t++) {
        int c = tid + t * 256;
        out[row * DD + c] = (v[t] - mu) * inv * lg[c] + lb[c];
    }
}

// ---------------------------------------------------------------------------
extern "C" void kernel_launch(void* const* d_in, const int* in_sizes, int n_in,
                              void* d_out, int out_size)
{
    const float* Q  = (const float*)d_in[0];
    const float* K  = (const float*)d_in[1];
    const float* V  = (const float*)d_in[2];
    const int*   pad = (const int*)d_in[3];
    const float* Wq = (const float*)d_in[4];
    const float* bq = (const float*)d_in[5];
    const float* Wk = (const float*)d_in[6];
    const float* bk = (const float*)d_in[7];
    const float* Wv = (const float*)d_in[8];
    const float* bv = (const float*)d_in[9];
    const float* Wo = (const float*)d_in[10];
    const float* bo = (const float*)d_in[11];
    const float* lg = (const float*)d_in[12];
    const float* lb = (const float*)d_in[13];
    float* out = (float*)d_out;

    float* attn = ((long long)out_size >= OUT_ELEMS + ATTN_ELEMS) ? (out + OUT_ELEMS)
                                                                  : nullptr;

    const int PROJ_SMEM   = (128 * 68 + 64 * 68) * 4;   // 52224
    const int SCORES_SMEM = (128 * 68 * 2) * 4;         // 69632
    const int CTX_SMEM    = (128 * 68 + 64 * 68) * 4;   // 52224
    cudaFuncSetAttribute(proj_kernel<0>, cudaFuncAttributeMaxDynamicSharedMemorySize, PROJ_SMEM);
    cudaFuncSetAttribute(proj_kernel<1>, cudaFuncAttributeMaxDynamicSharedMemorySize, PROJ_SMEM);
    cudaFuncSetAttribute(proj_kernel<2>, cudaFuncAttributeMaxDynamicSharedMemorySize, PROJ_SMEM);
    cudaFuncSetAttribute(proj_kernel<3>, cudaFuncAttributeMaxDynamicSharedMemorySize, PROJ_SMEM);
    cudaFuncSetAttribute(scores_kernel, cudaFuncAttributeMaxDynamicSharedMemorySize, SCORES_SMEM);
    cudaFuncSetAttribute(context_kernel, cudaFuncAttributeMaxDynamicSharedMemorySize, CTX_SMEM);

    dim3 gp(DD / 64, (BB * SS) / 128);          // (12, 64)
    proj_kernel<0><<<gp, 256, PROJ_SMEM>>>(Q, Wq, bq, nullptr);
    proj_kernel<1><<<gp, 256, PROJ_SMEM>>>(K, Wk, bk, nullptr);
    proj_kernel<2><<<gp, 256, PROJ_SMEM>>>(V, Wv, bv, nullptr);

    dim3 gs(SS / 128, SS / 128, BB * HH);       // (16, 16, 48)
    scores_kernel<<<gs, 256, SCORES_SMEM>>>(pad, attn);

    rowinv_kernel<<<(BB * HH * SS) / 256, 256>>>();

    dim3 gc(SS / 128, BB * HH);                 // (16, 48)
    context_kernel<<<gc, 256, CTX_SMEM>>>(attn);

    proj_kernel<3><<<gp, 256, PROJ_SMEM>>>(nullptr, Wo, bo, Q);

    ln_kernel<<<BB * SS, 256>>>(lg, lb, out);
}